// round 14
// baseline (speedup 1.0000x reference)
#include <cuda_runtime.h>
#include <cuda_bf16.h>
#include <cuda_fp16.h>
#include <math.h>
#include <stdint.h>

// ---------------- problem constants ----------------
#define NPIX 131072
#define DIMV 720
#define KP   768          // K padded (24 chunks of 32)
#define NCLS 19
#define NPRO 10
#define KM   190
#define SKEPS_INV 20.0f
#define BSCALE 1024.0f
#define INV_BSCALE (1.0f / 1024.0f)
#define TAU_PRED 5e-5f
#define TAU_IDX  2e-3f

// output layout (fp32): out_seg[N,19] | contrast[N,190] | proto_target[N] | protos_new[190,720]
#define OFF_SEG 0
#define OFF_CON ((size_t)NPIX * 19)
#define OFF_PT  (OFF_CON + (size_t)NPIX * 190)
#define OFF_PN  (OFF_PT + (size_t)NPIX)

// ---------------- device scratch ----------------
__device__ uint4 g_ahi4[(size_t)NPIX * 96];   // pixel embeddings fp16 [N][768]
__device__ uint4 g_Bh4[192 * 96];             // protos fp16 hi of 1024*P [192][768]
__device__ uint4 g_Bl4[192 * 96];             // protos fp16 lo
__device__ float g_Pn[KM * DIMV];             // normalized protos fp32 (exact path)
__device__ float g_E[(size_t)NPIX * NPRO];    // exp(sim_gt/eps)
__device__ float g_S[KM];
__device__ float g_b[KM];
__device__ float g_Bk[NCLS];
__device__ float g_nkm[KM];
__device__ float g_f[KM * DIMV];
__device__ unsigned char g_corr[NPIX];
__device__ unsigned char g_idx[NPIX];
__device__ int4 g_fixA[NPIX];                 // {n, k1, k2, k3}
__device__ int4 g_fixB[NPIX];                 // {n, m1, m2, m3}
__device__ int g_nfixA;
__device__ int g_nfixB;

// ---------------- generic helpers ----------------
__device__ __forceinline__ float warp_sum(float v) {
    #pragma unroll
    for (int o = 16; o; o >>= 1) v += __shfl_xor_sync(0xffffffffu, v, o);
    return v;
}

__device__ __forceinline__ float block_sum_256(float v) {
    __shared__ float sh[8];
    int lane = threadIdx.x & 31, w = threadIdx.x >> 5;
    v = warp_sum(v);
    if (lane == 0) sh[w] = v;
    __syncthreads();
    float r = 0.f;
    if (threadIdx.x < 8) r = sh[threadIdx.x];
    if (w == 0) {
        #pragma unroll
        for (int o = 4; o; o >>= 1) r += __shfl_xor_sync(0xffffffffu, r, o);
    }
    if (threadIdx.x == 0) sh[0] = r;
    __syncthreads();
    r = sh[0];
    __syncthreads();
    return r;
}

__device__ __forceinline__ uint32_t smem_u32(const void* p) {
    uint32_t a;
    asm("{ .reg .u64 t; cvta.to.shared.u64 t, %1; cvt.u32.u64 %0, t; }" : "=r"(a) : "l"(p));
    return a;
}

// warp-cooperative exact fp32 LN+l2 embedding of pixel n
__device__ __forceinline__ void exact_embed(const float* __restrict__ x,
                                            const float* __restrict__ fg,
                                            const float* __restrict__ fb,
                                            int n, int lane, float* av) {
    const float* xr = x + (size_t)n * DIMV;
    float s = 0.f;
    #pragma unroll
    for (int i = 0; i < 23; ++i) {
        int d = lane + 32 * i;
        float t = (d < DIMV) ? xr[d] : 0.f;
        av[i] = t; s += t;
    }
    s = warp_sum(s);
    float mu = s / (float)DIMV;
    float sq = 0.f;
    #pragma unroll
    for (int i = 0; i < 23; ++i) {
        int d = lane + 32 * i;
        if (d < DIMV) { float t = av[i] - mu; sq += t * t; }
    }
    sq = warp_sum(sq);
    float r = rsqrtf(sq / (float)DIMV + 1e-5f);
    float ny = 0.f;
    #pragma unroll
    for (int i = 0; i < 23; ++i) {
        int d = lane + 32 * i;
        if (d < DIMV) {
            float y = (av[i] - mu) * r * fg[d] + fb[d];
            av[i] = y; ny += y * y;
        } else av[i] = 0.f;
    }
    ny = warp_sum(ny);
    float inv = 1.f / fmaxf(sqrtf(ny), 1e-12f);
    #pragma unroll
    for (int i = 0; i < 23; ++i) av[i] *= inv;
}

// ---------------- PTX macros ----------------
#define LDSM4(r, addr) \
    asm volatile("ldmatrix.sync.aligned.m8n8.x4.shared.b16 {%0,%1,%2,%3}, [%4];" \
        : "=r"((r)[0]), "=r"((r)[1]), "=r"((r)[2]), "=r"((r)[3]) : "r"(addr))

#define MMA_FP16(c, a, b0, b1) \
    asm volatile("mma.sync.aligned.m16n8k16.row.col.f32.f16.f16.f32 " \
        "{%0,%1,%2,%3}, {%4,%5,%6,%7}, {%8,%9}, {%0,%1,%2,%3};" \
        : "+f"((c)[0]), "+f"((c)[1]), "+f"((c)[2]), "+f"((c)[3]) \
        : "r"((a)[0]), "r"((a)[1]), "r"((a)[2]), "r"((a)[3]), "r"(b0), "r"(b1))

#define CP16(dst, src) \
    asm volatile("cp.async.cg.shared.global [%0], [%1], 16;" :: "r"(dst), "l"(src) : "memory")

// ---------------- 0: zero accumulators ----------------
__global__ void zero_kernel() {
    int i = blockIdx.x * blockDim.x + threadIdx.x;
    int stride = gridDim.x * blockDim.x;
    for (int j = i; j < KM * DIMV; j += stride) g_f[j] = 0.f;
    for (int j = i; j < KM; j += stride) { g_S[j] = 0.f; g_nkm[j] = 0.f; }
    for (int j = i; j < NCLS; j += stride) g_Bk[j] = 0.f;
    if (i == 0) { g_nfixA = 0; g_nfixB = 0; }
}

// ---------------- 1: l2-normalize prototypes -> fp16 hi/lo (x1024) + fp32 ----------------
__global__ void norm_protos(const float* __restrict__ proto) {
    int row = blockIdx.x;                   // 0..191 (190,191 zero pad)
    __half* hi = (__half*)g_Bh4 + (size_t)row * KP;
    __half* lo = (__half*)g_Bl4 + (size_t)row * KP;
    float inv = 0.f;
    const float* p = proto + (size_t)row * DIMV;
    if (row < KM) {
        float sq = 0.f;
        for (int d = threadIdx.x; d < DIMV; d += blockDim.x) { float v = p[d]; sq += v * v; }
        sq = block_sum_256(sq);
        inv = 1.f / fmaxf(sqrtf(sq), 1e-12f);
    } else {
        block_sum_256(0.f);
    }
    for (int d = threadIdx.x; d < KP; d += blockDim.x) {
        float v = (row < KM && d < DIMV) ? p[d] * inv : 0.f;
        float s = v * BSCALE;
        __half h = __float2half(s);
        hi[d] = h;
        lo[d] = __float2half(s - __half2float(h));
        if (row < KM && d < DIMV) g_Pn[(size_t)row * DIMV + d] = v;
    }
}

// ---------------- 2: per-pixel LN + L2 -> fp16 (vectorized float4) ----------------
__global__ void prep_pixels(const float* __restrict__ x,
                            const float* __restrict__ fg,
                            const float* __restrict__ fb) {
    __shared__ uint4 sh4[8][96];             // [warp][96 uint4]
    int w = threadIdx.x >> 5, lane = threadIdx.x & 31;
    int row = blockIdx.x * 8 + w;
    const float4* xr4 = (const float4*)(x + (size_t)row * DIMV);   // 180 float4
    const float4* fg4 = (const float4*)fg;
    const float4* fb4 = (const float4*)fb;

    float4 v[6];
    float s = 0.f;
    #pragma unroll
    for (int i = 0; i < 6; ++i) {
        int q = lane + 32 * i;
        if (q < 180) {
            float4 t = xr4[q];
            v[i] = t; s += t.x + t.y + t.z + t.w;
        } else v[i] = make_float4(0.f, 0.f, 0.f, 0.f);
    }
    s = warp_sum(s);
    float mu = s / (float)DIMV;
    float sq = 0.f;
    #pragma unroll
    for (int i = 0; i < 6; ++i) {
        int q = lane + 32 * i;
        if (q < 180) {
            float a = v[i].x - mu, b = v[i].y - mu, c = v[i].z - mu, d = v[i].w - mu;
            sq += a * a + b * b + c * c + d * d;
        }
    }
    sq = warp_sum(sq);
    float r = rsqrtf(sq / (float)DIMV + 1e-5f);
    float ny = 0.f;
    #pragma unroll
    for (int i = 0; i < 6; ++i) {
        int q = lane + 32 * i;
        if (q < 180) {
            float4 g = fg4[q], b4 = fb4[q];
            float4 y;
            y.x = (v[i].x - mu) * r * g.x + b4.x;
            y.y = (v[i].y - mu) * r * g.y + b4.y;
            y.z = (v[i].z - mu) * r * g.z + b4.z;
            y.w = (v[i].w - mu) * r * g.w + b4.w;
            v[i] = y;
            ny += y.x * y.x + y.y * y.y + y.z * y.z + y.w * y.w;
        }
    }
    ny = warp_sum(ny);
    float inv = 1.f / fmaxf(sqrtf(ny), 1e-12f);

    uint2* sh2 = (uint2*)sh4[w];             // 192 uint2
    #pragma unroll
    for (int i = 0; i < 6; ++i) {
        int q = lane + 32 * i;
        if (q < 180) {
            __half2 h0 = __floats2half2_rn(v[i].x * inv, v[i].y * inv);
            __half2 h1 = __floats2half2_rn(v[i].z * inv, v[i].w * inv);
            uint2 u;
            u.x = *(uint32_t*)&h0;
            u.y = *(uint32_t*)&h1;
            sh2[q] = u;
        } else if (q < 192) {
            sh2[q] = make_uint2(0u, 0u);     // pad [720,768)
        }
    }
    __syncwarp();
    const uint4* s0 = sh4[w];
    #pragma unroll
    for (int chunk = 0; chunk < 3; ++chunk)
        g_ahi4[(size_t)row * 96 + chunk * 32 + lane] = s0[chunk * 32 + lane];
}

// ---------------- 3: HMMA GEMM (2-term fp16) + fused epilogue — R10/R12 config ----------------
#define STG 40960      // stage: A 10240 | Bh 15360 | Bl 15360 (pitch 80B)
#define NSTG 3
#define DYN_SMEM (NSTG * STG)

__global__ void __launch_bounds__(512, 1) gemm_epi(const float* __restrict__ mg,
                                                   const float* __restrict__ mb,
                                                   const float* __restrict__ pg,
                                                   const float* __restrict__ pb,
                                                   const int*   __restrict__ gt,
                                                   float* __restrict__ out) {
    extern __shared__ char dsm[];
    __shared__ float sPg[KM], sPb[KM], sMg[NCLS], sMb[NCLS], bk[NCLS], Sl[KM];
    __shared__ float seg_s[128 * NCLS];
    __shared__ float e_s[128 * NPRO];

    uint32_t tb = smem_u32(dsm);
    int t = threadIdx.x, lane = t & 31, w = t >> 5;
    int m0 = (w & 3) * 32, n0 = (w >> 2) * 48;
    int bm0 = blockIdx.x * 128;

    if (t < KM) { sPg[t] = pg[t]; sPb[t] = pb[t]; Sl[t] = 0.f; }
    if (t < NCLS) { sMg[t] = mg[t]; sMb[t] = mb[t]; bk[t] = 0.f; }

    float acc[2][6][4];
    #pragma unroll
    for (int a = 0; a < 2; ++a)
        #pragma unroll
        for (int b = 0; b < 6; ++b)
            #pragma unroll
            for (int c = 0; c < 4; ++c) acc[a][b][c] = 0.f;

    uint32_t aRow = (uint32_t)(m0 + (lane & 15)) * 80 + ((lane >> 4) << 4);
    uint32_t bRow = (uint32_t)(n0 + (lane & 15)) * 80 + ((lane >> 4) << 4);

    auto load_stage = [&](int c, int buf) {
        uint32_t st = tb + buf * STG;
        {   // A: 128 rows x 4 uint4 = 512 units
            int row = t >> 2, q = t & 3;
            const uint4* src = g_ahi4 + (size_t)(bm0 + row) * 96 + c * 4 + q;
            CP16(st + row * 80 + q * 16, src);
        }
        #pragma unroll
        for (int i = 0; i < 3; ++i) {  // B: 2 splits x 192 rows x 4 = 1536 units
            int u = t + i * 512;
            int split = (u >= 768); int rem = u - split * 768;
            int row = rem >> 2, q = rem & 3;
            const uint4* src = (split ? g_Bl4 : g_Bh4) + (size_t)row * 96 + c * 4 + q;
            CP16(st + 10240 + split * 15360 + row * 80 + q * 16, src);
        }
        asm volatile("cp.async.commit_group;" ::: "memory");
    };

    auto compute = [&](int buf) {
        uint32_t stA = tb + buf * STG;
        uint32_t stB = stA + 10240;
        #pragma unroll
        for (int ks = 0; ks < 2; ++ks) {
            uint32_t kb = ks * 32;
            uint32_t ah[2][4];
            LDSM4(ah[0], stA + aRow + kb);
            LDSM4(ah[1], stA + aRow + 1280 + kb);
            #pragma unroll
            for (int p = 0; p < 3; ++p) {
                uint32_t bh[4], bl[4];
                LDSM4(bh, stB + bRow + p * 1280 + kb);
                LDSM4(bl, stB + 15360 + bRow + p * 1280 + kb);
                #pragma unroll
                for (int mt = 0; mt < 2; ++mt) {
                    MMA_FP16(acc[mt][2 * p],     ah[mt], bh[0], bh[2]);
                    MMA_FP16(acc[mt][2 * p + 1], ah[mt], bh[1], bh[3]);
                    MMA_FP16(acc[mt][2 * p],     ah[mt], bl[0], bl[2]);
                    MMA_FP16(acc[mt][2 * p + 1], ah[mt], bl[1], bl[3]);
                }
            }
        }
    };

    load_stage(0, 0);
    load_stage(1, 1);
    #pragma unroll 1
    for (int c = 0; c < 24; ++c) {
        if (c < 23) asm volatile("cp.async.wait_group 1;" ::: "memory");
        else        asm volatile("cp.async.wait_group 0;" ::: "memory");
        __syncthreads();
        if (c + 2 < 24) load_stage(c + 2, (c + 2) % NSTG);
        compute(c % NSTG);
    }
    __syncthreads();

    // ---------------- epilogue ----------------
    float* sim = (float*)dsm;     // [128][195]
    {
        int r0 = lane >> 2, cc = (lane & 3) * 2;
        #pragma unroll
        for (int mt = 0; mt < 2; ++mt) {
            #pragma unroll
            for (int j = 0; j < 6; ++j) {
                int row = m0 + mt * 16 + r0;
                int col = n0 + j * 8 + cc;
                sim[row * 195 + col]           = acc[mt][j][0] * INV_BSCALE;
                sim[row * 195 + col + 1]       = acc[mt][j][1] * INV_BSCALE;
                sim[(row + 8) * 195 + col]     = acc[mt][j][2] * INV_BSCALE;
                sim[(row + 8) * 195 + col + 1] = acc[mt][j][3] * INV_BSCALE;
            }
        }
    }
    __syncthreads();

    if (t < 128) {
        int n = bm0 + t;
        int gtn = gt[n];
        float s = 0.f, sq = 0.f, s19 = 0.f, sq19 = 0.f;
        float ev[NPRO];
        #pragma unroll
        for (int m = 0; m < NPRO; ++m) ev[m] = 0.f;
        float v1 = -1e30f, v2 = -1e30f, v3 = -1e30f;
        int   i1 = 0, i2 = 0, i3 = 0;
        for (int k = 0; k < NCLS; ++k) {
            float mx = -1e30f;
            #pragma unroll
            for (int m = 0; m < NPRO; ++m) {
                float v = sim[t * 195 + k * NPRO + m];
                s += v; sq += v * v;
                mx = fmaxf(mx, v);
                if (k == gtn) ev[m] = v;
            }
            seg_s[t * NCLS + k] = mx;
            s19 += mx; sq19 += mx * mx;
            if (mx > v1)      { v3 = v2; i3 = i2; v2 = v1; i2 = i1; v1 = mx; i1 = k; }
            else if (mx > v2) { v3 = v2; i3 = i2; v2 = mx; i2 = k; }
            else if (mx > v3) { v3 = mx; i3 = k; }
        }
        float mu19 = s19 / (float)NCLS;
        float var19 = fmaxf(sq19 / (float)NCLS - mu19 * mu19, 0.f);
        float rv19 = rsqrtf(var19 + 1e-5f);
        float best = -1e30f; int bi = 0;
        for (int k = 0; k < NCLS; ++k) {
            float o = (seg_s[t * NCLS + k] - mu19) * rv19 * sMg[k] + sMb[k];
            seg_s[t * NCLS + k] = o;
            if (o > best) { best = o; bi = k; }
        }
        g_corr[n] = (bi == gtn) ? 1 : 0;
        if (v1 - v2 < TAU_PRED) {
            int ii = atomicAdd(&g_nfixA, 1);
            g_fixA[ii] = make_int4(n, i1, i2, i3);
        }
        atomicAdd(&bk[gtn], 1.f);
        #pragma unroll
        for (int m = 0; m < NPRO; ++m) {
            float e = expf(ev[m] * SKEPS_INV);
            e_s[t * NPRO + m] = e;
            atomicAdd(&Sl[gtn * NPRO + m], e);
        }
        float mu = s / (float)KM;
        float var = fmaxf(sq / (float)KM - mu * mu, 0.f);
        float rv = rsqrtf(var + 1e-5f);
        for (int j = 0; j < KM; ++j)
            sim[t * 195 + j] = (sim[t * 195 + j] - mu) * rv * sPg[j] + sPb[j];
    }
    __syncthreads();

    for (int idx = t; idx < 128 * KM; idx += 512) {
        int row = idx / KM, j = idx - row * KM;
        out[OFF_CON + (size_t)bm0 * KM + idx] = sim[row * 195 + j];
    }
    for (int idx = t; idx < 128 * NCLS; idx += 512)
        out[OFF_SEG + (size_t)bm0 * NCLS + idx] = seg_s[idx];
    for (int idx = t; idx < 128 * NPRO; idx += 512)
        g_E[(size_t)bm0 * NPRO + idx] = e_s[idx];
    if (t < NCLS) atomicAdd(&g_Bk[t], bk[t]);
    if (t < KM) atomicAdd(&g_S[t], Sl[t]);
}

// ---------------- 3b: exact pred recompute — 10 parallel partial sums per class ----------------
__global__ void pred_fix(const float* __restrict__ x, const float* __restrict__ fg,
                         const float* __restrict__ fb, const int* __restrict__ gt) {
    int gw = (blockIdx.x * blockDim.x + threadIdx.x) >> 5;
    int lane = threadIdx.x & 31;
    int nwarps = (gridDim.x * blockDim.x) >> 5;
    int nfix = g_nfixA;
    for (int i = gw; i < nfix; i += nwarps) {
        int4 rec = g_fixA[i];
        int n = rec.x;
        float av[23];
        exact_embed(x, fg, fb, n, lane, av);
        int cand[3] = {rec.y, rec.z, rec.w};
        float best = -1e30f; int bi = 0;
        #pragma unroll
        for (int cc = 0; cc < 3; ++cc) {
            int k = cand[cc];
            const float* base = g_Pn + (size_t)k * NPRO * DIMV;
            float sm[NPRO];
            #pragma unroll
            for (int m = 0; m < NPRO; ++m) sm[m] = 0.f;
            #pragma unroll
            for (int j = 0; j < 23; ++j) {
                int d = lane + 32 * j;
                if (d < DIMV) {
                    float a = av[j];
                    #pragma unroll
                    for (int m = 0; m < NPRO; ++m)
                        sm[m] = fmaf(a, base[m * DIMV + d], sm[m]);
                }
            }
            // 10 interleaved warp reductions (independent shuffle chains)
            #pragma unroll
            for (int o = 16; o; o >>= 1) {
                #pragma unroll
                for (int m = 0; m < NPRO; ++m)
                    sm[m] += __shfl_xor_sync(0xffffffffu, sm[m], o);
            }
            float mx = sm[0];
            #pragma unroll
            for (int m = 1; m < NPRO; ++m) mx = fmaxf(mx, sm[m]);
            if (mx > best) { best = mx; bi = k; }
        }
        if (lane == 0) g_corr[n] = (bi == gt[n]) ? 1 : 0;
    }
}

// ---------------- 4: Sinkhorn column-sum accumulation (passes 1,2) ----------------
__global__ void sk_accum(const int* __restrict__ gt) {
    __shared__ float Sl[KM];
    int t = threadIdx.x;
    if (t < KM) Sl[t] = 0.f;
    __syncthreads();
    int n = blockIdx.x * blockDim.x + t;
    if (n < NPIX) {
        int k = gt[n];
        const float* E = g_E + (size_t)n * NPRO;
        float e[NPRO];
        #pragma unroll
        for (int m = 0; m < NPRO; ++m) e[m] = E[m];
        const float* bb = g_b + k * NPRO;
        float d = 0.f;
        #pragma unroll
        for (int m = 0; m < NPRO; ++m) d += e[m] * bb[m];
        float a = 1.f / (g_Bk[k] * d);
        #pragma unroll
        for (int m = 0; m < NPRO; ++m) atomicAdd(&Sl[k * NPRO + m], e[m] * a);
    }
    __syncthreads();
    if (t < KM) atomicAdd(&g_S[t], Sl[t]);
}

__global__ void sk_fin() {
    int t = threadIdx.x;
    if (t < KM) {
        float s = g_S[t];
        g_b[t] = (s > 0.f) ? 1.f / (10.f * s) : 0.f;
        g_S[t] = 0.f;
    }
}

// ---------------- 5: hard assignment + proto_target (top-3 flagging) ----------------
__global__ void sk_final(const int* __restrict__ gt, float* __restrict__ out) {
    int n = blockIdx.x * blockDim.x + threadIdx.x;
    if (n >= NPIX) return;
    int k = gt[n];
    const float* E = g_E + (size_t)n * NPRO;
    const float* bb = g_b + k * NPRO;
    float w1 = -1.f, w2 = -1.f, w3 = -1.f;
    int m1 = 0, m2 = 0, m3 = 0;
    #pragma unroll
    for (int m = 0; m < NPRO; ++m) {
        float wv = E[m] * bb[m];
        if (wv > w1)      { w3 = w2; m3 = m2; w2 = w1; m2 = m1; w1 = wv; m1 = m; }
        else if (wv > w2) { w3 = w2; m3 = m2; w2 = wv; m2 = m; }
        else if (wv > w3) { w3 = wv; m3 = m; }
    }
    out[OFF_PT + n] = (float)(m1 + NPRO * k);
    g_idx[n] = (unsigned char)m1;
    if (w1 - w2 <= TAU_IDX * w1) {
        int ii = atomicAdd(&g_nfixB, 1);
        g_fixB[ii] = make_int4(n, m1, m2, m3);
    }
}

// ---------------- 5b: exact proto-idx recompute — 3 parallel sums ----------------
__global__ void idx_fix(const float* __restrict__ x, const float* __restrict__ fg,
                        const float* __restrict__ fb, const int* __restrict__ gt,
                        float* __restrict__ out) {
    int gw = (blockIdx.x * blockDim.x + threadIdx.x) >> 5;
    int lane = threadIdx.x & 31;
    int nwarps = (gridDim.x * blockDim.x) >> 5;
    int nfix = g_nfixB;
    for (int i = gw; i < nfix; i += nwarps) {
        int4 rec = g_fixB[i];
        int n = rec.x;
        int k = gt[n];
        float av[23];
        exact_embed(x, fg, fb, n, lane, av);
        int cand[3] = {rec.y, rec.z, rec.w};
        float sm[3] = {0.f, 0.f, 0.f};
        const float* p0 = g_Pn + (size_t)(k * NPRO + cand[0]) * DIMV;
        const float* p1 = g_Pn + (size_t)(k * NPRO + cand[1]) * DIMV;
        const float* p2 = g_Pn + (size_t)(k * NPRO + cand[2]) * DIMV;
        #pragma unroll
        for (int j = 0; j < 23; ++j) {
            int d = lane + 32 * j;
            if (d < DIMV) {
                float a = av[j];
                sm[0] = fmaf(a, p0[d], sm[0]);
                sm[1] = fmaf(a, p1[d], sm[1]);
                sm[2] = fmaf(a, p2[d], sm[2]);
            }
        }
        #pragma unroll
        for (int o = 16; o; o >>= 1) {
            #pragma unroll
            for (int cc = 0; cc < 3; ++cc)
                sm[cc] += __shfl_xor_sync(0xffffffffu, sm[cc], o);
        }
        float w1 = -1.f; int bi = 0;
        #pragma unroll
        for (int cc = 0; cc < 3; ++cc) {
            int m = cand[cc];
            float wv = expf(sm[cc] * SKEPS_INV) * g_b[k * NPRO + m];
            if (wv > w1 || (wv == w1 && m < bi)) { w1 = wv; bi = m; }
        }
        if (lane == 0) {
            g_idx[n] = (unsigned char)bi;
            out[OFF_PT + n] = (float)(bi + NPRO * k);
        }
    }
}

// ---------------- 6: accumulate f over correct pixels (exact, + n_km) ----------------
__global__ void f_accum(const float* __restrict__ x, const float* __restrict__ fg,
                        const float* __restrict__ fb, const int* __restrict__ gt) {
    int warp = (blockIdx.x * blockDim.x + threadIdx.x) >> 5;
    int lane = threadIdx.x & 31;
    if (warp >= NPIX) return;
    if (!g_corr[warp]) return;
    int k = gt[warp], m = g_idx[warp];
    if (lane == 0) atomicAdd(&g_nkm[k * NPRO + m], 1.f);
    float av[23];
    exact_embed(x, fg, fb, warp, lane, av);
    float* f = g_f + (size_t)(k * NPRO + m) * DIMV;
    #pragma unroll
    for (int i = 0; i < 23; ++i) {
        int d = lane + 32 * i;
        if (d < DIMV) atomicAdd(&f[d], av[i]);
    }
}

// ---------------- 7: prototype EMA update ----------------
__global__ void update_protos(float* __restrict__ out) {
    int row = blockIdx.x;                 // 0..189
    int k = row / NPRO;
    const float* f = g_f + (size_t)row * DIMV;
    const float* p = g_Pn + (size_t)row * DIMV;

    float sq = 0.f;
    for (int d = threadIdx.x; d < DIMV; d += blockDim.x) { float v = f[d]; sq += v * v; }
    sq = block_sum_256(sq);
    float invf = 1.f / fmaxf(sqrtf(sq), 1e-12f);

    float nk = g_nkm[row];
    float ksum = 0.f;
    #pragma unroll
    for (int m = 0; m < NPRO; ++m) ksum += g_nkm[k * NPRO + m];
    bool valid = (nk != 0.f) && (ksum > 0.f);

    float squ = 0.f;
    for (int d = threadIdx.x; d < DIMV; d += blockDim.x) {
        float pv = p[d];
        float u = valid ? (0.999f * pv + 0.001f * f[d] * invf) : pv;
        squ += u * u;
    }
    squ = block_sum_256(squ);
    float invu = 1.f / fmaxf(sqrtf(squ), 1e-12f);
    for (int d = threadIdx.x; d < DIMV; d += blockDim.x) {
        float pv = p[d];
        float u = valid ? (0.999f * pv + 0.001f * f[d] * invf) : pv;
        out[OFF_PN + (size_t)row * DIMV + d] = u * invu;
    }
}

// ---------------- launch ----------------
extern "C" void kernel_launch(void* const* d_in, const int* in_sizes, int n_in,
                              void* d_out, int out_size) {
    const float* x     = (const float*)d_in[0];
    const float* proto = (const float*)d_in[1];
    const float* fn_g  = (const float*)d_in[2];
    const float* fn_b  = (const float*)d_in[3];
    const float* mn_g  = (const float*)d_in[4];
    const float* mn_b  = (const float*)d_in[5];
    const float* pn_g  = (const float*)d_in[6];
    const float* pn_b  = (const float*)d_in[7];
    const int*   gt    = (const int*)d_in[8];
    float* out = (float*)d_out;

    cudaFuncSetAttribute(gemm_epi, cudaFuncAttributeMaxDynamicSharedMemorySize, DYN_SMEM);

    zero_kernel<<<540, 256>>>();
    norm_protos<<<192, 256>>>(proto);
    prep_pixels<<<NPIX / 8, 256>>>(x, fn_g, fn_b);
    gemm_epi<<<NPIX / 128, 512, DYN_SMEM>>>(mn_g, mn_b, pn_g, pn_b, gt, out);
    pred_fix<<<296, 256>>>(x, fn_g, fn_b, gt);
    sk_fin<<<1, 192>>>();
    sk_accum<<<NPIX / 256, 256>>>(gt);
    sk_fin<<<1, 192>>>();
    sk_accum<<<NPIX / 256, 256>>>(gt);
    sk_fin<<<1, 192>>>();
    sk_final<<<NPIX / 256, 256>>>(gt, out);
    idx_fix<<<296, 256>>>(x, fn_g, fn_b, gt, out);
    f_accum<<<NPIX / 8, 256>>>(x, fn_g, fn_b, gt);
    update_protos<<<KM, 256>>>(out);
}

// round 15
// speedup vs baseline: 1.0411x; 1.0411x over previous
#include <cuda_runtime.h>
#include <cuda_bf16.h>
#include <cuda_fp16.h>
#include <math.h>
#include <stdint.h>

// ---------------- problem constants ----------------
#define NPIX 131072
#define DIMV 720
#define KP   768          // K padded (24 chunks of 32)
#define NCLS 19
#define NPRO 10
#define KM   190
#define SKEPS_INV 20.0f
#define BSCALE 1024.0f
#define INV_BSCALE (1.0f / 1024.0f)
#define TAU_PRED 1e-4f
#define TAU_IDX  2e-3f

// output layout (fp32): out_seg[N,19] | contrast[N,190] | proto_target[N] | protos_new[190,720]
#define OFF_SEG 0
#define OFF_CON ((size_t)NPIX * 19)
#define OFF_PT  (OFF_CON + (size_t)NPIX * 190)
#define OFF_PN  (OFF_PT + (size_t)NPIX)

// ---------------- device scratch ----------------
__device__ uint4 g_ahi4[(size_t)NPIX * 96];   // pixel embeddings fp16 [N][768]
__device__ uint4 g_Bh4[192 * 96];             // protos fp16 hi of 1024*P [192][768]
__device__ uint4 g_Bl4[192 * 96];             // protos fp16 lo
__device__ float g_Pn[KM * DIMV];             // normalized protos fp32 (exact path)
__device__ float g_E[(size_t)NPIX * NPRO];    // exp(sim_gt/eps)
__device__ float g_S[KM];
__device__ float g_b[KM];
__device__ float g_Bk[NCLS];
__device__ float g_nkm[KM];
__device__ float g_f[KM * DIMV];
__device__ unsigned char g_idx[NPIX];
__device__ int4 g_fixA[NPIX];                 // {n, k1, k2, k3}
__device__ int4 g_fixB[NPIX];                 // {n, m1, m2, m3}
__device__ int g_corrList[NPIX];              // compact list of correct pixels
__device__ int g_nfixA;
__device__ int g_nfixB;
__device__ int g_ncorr;

// ---------------- generic helpers ----------------
__device__ __forceinline__ float warp_sum(float v) {
    #pragma unroll
    for (int o = 16; o; o >>= 1) v += __shfl_xor_sync(0xffffffffu, v, o);
    return v;
}

__device__ __forceinline__ float block_sum_256(float v) {
    __shared__ float sh[8];
    int lane = threadIdx.x & 31, w = threadIdx.x >> 5;
    v = warp_sum(v);
    if (lane == 0) sh[w] = v;
    __syncthreads();
    float r = 0.f;
    if (threadIdx.x < 8) r = sh[threadIdx.x];
    if (w == 0) {
        #pragma unroll
        for (int o = 4; o; o >>= 1) r += __shfl_xor_sync(0xffffffffu, r, o);
    }
    if (threadIdx.x == 0) sh[0] = r;
    __syncthreads();
    r = sh[0];
    __syncthreads();
    return r;
}

__device__ __forceinline__ uint32_t smem_u32(const void* p) {
    uint32_t a;
    asm("{ .reg .u64 t; cvta.to.shared.u64 t, %1; cvt.u32.u64 %0, t; }" : "=r"(a) : "l"(p));
    return a;
}

// warp-cooperative exact fp32 LN+l2 embedding of pixel n
__device__ __forceinline__ void exact_embed(const float* __restrict__ x,
                                            const float* __restrict__ fg,
                                            const float* __restrict__ fb,
                                            int n, int lane, float* av) {
    const float* xr = x + (size_t)n * DIMV;
    float s = 0.f;
    #pragma unroll
    for (int i = 0; i < 23; ++i) {
        int d = lane + 32 * i;
        float t = (d < DIMV) ? xr[d] : 0.f;
        av[i] = t; s += t;
    }
    s = warp_sum(s);
    float mu = s / (float)DIMV;
    float sq = 0.f;
    #pragma unroll
    for (int i = 0; i < 23; ++i) {
        int d = lane + 32 * i;
        if (d < DIMV) { float t = av[i] - mu; sq += t * t; }
    }
    sq = warp_sum(sq);
    float r = rsqrtf(sq / (float)DIMV + 1e-5f);
    float ny = 0.f;
    #pragma unroll
    for (int i = 0; i < 23; ++i) {
        int d = lane + 32 * i;
        if (d < DIMV) {
            float y = (av[i] - mu) * r * fg[d] + fb[d];
            av[i] = y; ny += y * y;
        } else av[i] = 0.f;
    }
    ny = warp_sum(ny);
    float inv = 1.f / fmaxf(sqrtf(ny), 1e-12f);
    #pragma unroll
    for (int i = 0; i < 23; ++i) av[i] *= inv;
}

// ---------------- PTX macros ----------------
#define LDSM4(r, addr) \
    asm volatile("ldmatrix.sync.aligned.m8n8.x4.shared.b16 {%0,%1,%2,%3}, [%4];" \
        : "=r"((r)[0]), "=r"((r)[1]), "=r"((r)[2]), "=r"((r)[3]) : "r"(addr))

#define MMA_FP16(c, a, b0, b1) \
    asm volatile("mma.sync.aligned.m16n8k16.row.col.f32.f16.f16.f32 " \
        "{%0,%1,%2,%3}, {%4,%5,%6,%7}, {%8,%9}, {%0,%1,%2,%3};" \
        : "+f"((c)[0]), "+f"((c)[1]), "+f"((c)[2]), "+f"((c)[3]) \
        : "r"((a)[0]), "r"((a)[1]), "r"((a)[2]), "r"((a)[3]), "r"(b0), "r"(b1))

#define CP16(dst, src) \
    asm volatile("cp.async.cg.shared.global [%0], [%1], 16;" :: "r"(dst), "l"(src) : "memory")

// ---------------- 0: zero accumulators ----------------
__global__ void zero_kernel() {
    int i = blockIdx.x * blockDim.x + threadIdx.x;
    int stride = gridDim.x * blockDim.x;
    for (int j = i; j < KM * DIMV; j += stride) g_f[j] = 0.f;
    for (int j = i; j < KM; j += stride) { g_S[j] = 0.f; g_nkm[j] = 0.f; }
    for (int j = i; j < NCLS; j += stride) g_Bk[j] = 0.f;
    if (i == 0) { g_nfixA = 0; g_nfixB = 0; g_ncorr = 0; }
}

// ---------------- 1: l2-normalize prototypes -> fp16 hi/lo (x1024) + fp32 ----------------
__global__ void norm_protos(const float* __restrict__ proto) {
    int row = blockIdx.x;                   // 0..191 (190,191 zero pad)
    __half* hi = (__half*)g_Bh4 + (size_t)row * KP;
    __half* lo = (__half*)g_Bl4 + (size_t)row * KP;
    float inv = 0.f;
    const float* p = proto + (size_t)row * DIMV;
    if (row < KM) {
        float sq = 0.f;
        for (int d = threadIdx.x; d < DIMV; d += blockDim.x) { float v = p[d]; sq += v * v; }
        sq = block_sum_256(sq);
        inv = 1.f / fmaxf(sqrtf(sq), 1e-12f);
    } else {
        block_sum_256(0.f);
    }
    for (int d = threadIdx.x; d < KP; d += blockDim.x) {
        float v = (row < KM && d < DIMV) ? p[d] * inv : 0.f;
        float s = v * BSCALE;
        __half h = __float2half(s);
        hi[d] = h;
        lo[d] = __float2half(s - __half2float(h));
        if (row < KM && d < DIMV) g_Pn[(size_t)row * DIMV + d] = v;
    }
}

// ---------------- 2: per-pixel LN + L2 -> fp16 (vectorized float4) ----------------
__global__ void prep_pixels(const float* __restrict__ x,
                            const float* __restrict__ fg,
                            const float* __restrict__ fb) {
    __shared__ uint4 sh4[8][96];             // [warp][96 uint4]
    int w = threadIdx.x >> 5, lane = threadIdx.x & 31;
    int row = blockIdx.x * 8 + w;
    const float4* xr4 = (const float4*)(x + (size_t)row * DIMV);   // 180 float4
    const float4* fg4 = (const float4*)fg;
    const float4* fb4 = (const float4*)fb;

    float4 v[6];
    float s = 0.f;
    #pragma unroll
    for (int i = 0; i < 6; ++i) {
        int q = lane + 32 * i;
        if (q < 180) {
            float4 t = xr4[q];
            v[i] = t; s += t.x + t.y + t.z + t.w;
        } else v[i] = make_float4(0.f, 0.f, 0.f, 0.f);
    }
    s = warp_sum(s);
    float mu = s / (float)DIMV;
    float sq = 0.f;
    #pragma unroll
    for (int i = 0; i < 6; ++i) {
        int q = lane + 32 * i;
        if (q < 180) {
            float a = v[i].x - mu, b = v[i].y - mu, c = v[i].z - mu, d = v[i].w - mu;
            sq += a * a + b * b + c * c + d * d;
        }
    }
    sq = warp_sum(sq);
    float r = rsqrtf(sq / (float)DIMV + 1e-5f);
    float ny = 0.f;
    #pragma unroll
    for (int i = 0; i < 6; ++i) {
        int q = lane + 32 * i;
        if (q < 180) {
            float4 g = fg4[q], b4 = fb4[q];
            float4 y;
            y.x = (v[i].x - mu) * r * g.x + b4.x;
            y.y = (v[i].y - mu) * r * g.y + b4.y;
            y.z = (v[i].z - mu) * r * g.z + b4.z;
            y.w = (v[i].w - mu) * r * g.w + b4.w;
            v[i] = y;
            ny += y.x * y.x + y.y * y.y + y.z * y.z + y.w * y.w;
        }
    }
    ny = warp_sum(ny);
    float inv = 1.f / fmaxf(sqrtf(ny), 1e-12f);

    uint2* sh2 = (uint2*)sh4[w];             // 192 uint2
    #pragma unroll
    for (int i = 0; i < 6; ++i) {
        int q = lane + 32 * i;
        if (q < 180) {
            __half2 h0 = __floats2half2_rn(v[i].x * inv, v[i].y * inv);
            __half2 h1 = __floats2half2_rn(v[i].z * inv, v[i].w * inv);
            uint2 u;
            u.x = *(uint32_t*)&h0;
            u.y = *(uint32_t*)&h1;
            sh2[q] = u;
        } else if (q < 192) {
            sh2[q] = make_uint2(0u, 0u);     // pad [720,768)
        }
    }
    __syncwarp();
    const uint4* s0 = sh4[w];
    #pragma unroll
    for (int chunk = 0; chunk < 3; ++chunk)
        g_ahi4[(size_t)row * 96 + chunk * 32 + lane] = s0[chunk * 32 + lane];
}

// ---------------- 3: HMMA GEMM (2-term fp16) + fused epilogue — R10/R12 config ----------------
#define STG 40960      // stage: A 10240 | Bh 15360 | Bl 15360 (pitch 80B)
#define NSTG 3
#define DYN_SMEM (NSTG * STG)

__global__ void __launch_bounds__(512, 1) gemm_epi(const float* __restrict__ mg,
                                                   const float* __restrict__ mb,
                                                   const float* __restrict__ pg,
                                                   const float* __restrict__ pb,
                                                   const int*   __restrict__ gt,
                                                   float* __restrict__ out) {
    extern __shared__ char dsm[];
    __shared__ float sPg[KM], sPb[KM], sMg[NCLS], sMb[NCLS], bk[NCLS], Sl[KM];
    __shared__ float seg_s[128 * NCLS];
    __shared__ float e_s[128 * NPRO];

    uint32_t tb = smem_u32(dsm);
    int t = threadIdx.x, lane = t & 31, w = t >> 5;
    int m0 = (w & 3) * 32, n0 = (w >> 2) * 48;
    int bm0 = blockIdx.x * 128;

    if (t < KM) { sPg[t] = pg[t]; sPb[t] = pb[t]; Sl[t] = 0.f; }
    if (t < NCLS) { sMg[t] = mg[t]; sMb[t] = mb[t]; bk[t] = 0.f; }

    float acc[2][6][4];
    #pragma unroll
    for (int a = 0; a < 2; ++a)
        #pragma unroll
        for (int b = 0; b < 6; ++b)
            #pragma unroll
            for (int c = 0; c < 4; ++c) acc[a][b][c] = 0.f;

    uint32_t aRow = (uint32_t)(m0 + (lane & 15)) * 80 + ((lane >> 4) << 4);
    uint32_t bRow = (uint32_t)(n0 + (lane & 15)) * 80 + ((lane >> 4) << 4);

    auto load_stage = [&](int c, int buf) {
        uint32_t st = tb + buf * STG;
        {   // A: 128 rows x 4 uint4 = 512 units
            int row = t >> 2, q = t & 3;
            const uint4* src = g_ahi4 + (size_t)(bm0 + row) * 96 + c * 4 + q;
            CP16(st + row * 80 + q * 16, src);
        }
        #pragma unroll
        for (int i = 0; i < 3; ++i) {  // B: 2 splits x 192 rows x 4 = 1536 units
            int u = t + i * 512;
            int split = (u >= 768); int rem = u - split * 768;
            int row = rem >> 2, q = rem & 3;
            const uint4* src = (split ? g_Bl4 : g_Bh4) + (size_t)row * 96 + c * 4 + q;
            CP16(st + 10240 + split * 15360 + row * 80 + q * 16, src);
        }
        asm volatile("cp.async.commit_group;" ::: "memory");
    };

    auto compute = [&](int buf) {
        uint32_t stA = tb + buf * STG;
        uint32_t stB = stA + 10240;
        #pragma unroll
        for (int ks = 0; ks < 2; ++ks) {
            uint32_t kb = ks * 32;
            uint32_t ah[2][4];
            LDSM4(ah[0], stA + aRow + kb);
            LDSM4(ah[1], stA + aRow + 1280 + kb);
            #pragma unroll
            for (int p = 0; p < 3; ++p) {
                uint32_t bh[4], bl[4];
                LDSM4(bh, stB + bRow + p * 1280 + kb);
                LDSM4(bl, stB + 15360 + bRow + p * 1280 + kb);
                #pragma unroll
                for (int mt = 0; mt < 2; ++mt) {
                    MMA_FP16(acc[mt][2 * p],     ah[mt], bh[0], bh[2]);
                    MMA_FP16(acc[mt][2 * p + 1], ah[mt], bh[1], bh[3]);
                    MMA_FP16(acc[mt][2 * p],     ah[mt], bl[0], bl[2]);
                    MMA_FP16(acc[mt][2 * p + 1], ah[mt], bl[1], bl[3]);
                }
            }
        }
    };

    load_stage(0, 0);
    load_stage(1, 1);
    #pragma unroll 1
    for (int c = 0; c < 24; ++c) {
        if (c < 23) asm volatile("cp.async.wait_group 1;" ::: "memory");
        else        asm volatile("cp.async.wait_group 0;" ::: "memory");
        __syncthreads();
        if (c + 2 < 24) load_stage(c + 2, (c + 2) % NSTG);
        compute(c % NSTG);
    }
    __syncthreads();

    // ---------------- epilogue ----------------
    float* sim = (float*)dsm;     // [128][195]
    {
        int r0 = lane >> 2, cc = (lane & 3) * 2;
        #pragma unroll
        for (int mt = 0; mt < 2; ++mt) {
            #pragma unroll
            for (int j = 0; j < 6; ++j) {
                int row = m0 + mt * 16 + r0;
                int col = n0 + j * 8 + cc;
                sim[row * 195 + col]           = acc[mt][j][0] * INV_BSCALE;
                sim[row * 195 + col + 1]       = acc[mt][j][1] * INV_BSCALE;
                sim[(row + 8) * 195 + col]     = acc[mt][j][2] * INV_BSCALE;
                sim[(row + 8) * 195 + col + 1] = acc[mt][j][3] * INV_BSCALE;
            }
        }
    }
    __syncthreads();

    if (t < 128) {
        int n = bm0 + t;
        int gtn = gt[n];
        float s = 0.f, sq = 0.f, s19 = 0.f, sq19 = 0.f;
        float ev[NPRO];
        #pragma unroll
        for (int m = 0; m < NPRO; ++m) ev[m] = 0.f;
        float v1 = -1e30f, v2 = -1e30f, v3 = -1e30f;
        int   i1 = 0, i2 = 0, i3 = 0;
        for (int k = 0; k < NCLS; ++k) {
            float mx = -1e30f;
            #pragma unroll
            for (int m = 0; m < NPRO; ++m) {
                float v = sim[t * 195 + k * NPRO + m];
                s += v; sq += v * v;
                mx = fmaxf(mx, v);
                if (k == gtn) ev[m] = v;
            }
            seg_s[t * NCLS + k] = mx;
            s19 += mx; sq19 += mx * mx;
            if (mx > v1)      { v3 = v2; i3 = i2; v2 = v1; i2 = i1; v1 = mx; i1 = k; }
            else if (mx > v2) { v3 = v2; i3 = i2; v2 = mx; i2 = k; }
            else if (mx > v3) { v3 = mx; i3 = k; }
        }
        float mu19 = s19 / (float)NCLS;
        float var19 = fmaxf(sq19 / (float)NCLS - mu19 * mu19, 0.f);
        float rv19 = rsqrtf(var19 + 1e-5f);
        float best = -1e30f; int bi = 0;
        for (int k = 0; k < NCLS; ++k) {
            float o = (seg_s[t * NCLS + k] - mu19) * rv19 * sMg[k] + sMb[k];
            seg_s[t * NCLS + k] = o;
            if (o > best) { best = o; bi = k; }
        }
        bool flagged = (v1 - v2 < TAU_PRED);
        if (flagged) {
            int ii = atomicAdd(&g_nfixA, 1);
            g_fixA[ii] = make_int4(n, i1, i2, i3);
        } else if (bi == gtn) {
            int ii = atomicAdd(&g_ncorr, 1);
            g_corrList[ii] = n;
        }
        atomicAdd(&bk[gtn], 1.f);
        #pragma unroll
        for (int m = 0; m < NPRO; ++m) {
            float e = expf(ev[m] * SKEPS_INV);
            e_s[t * NPRO + m] = e;
            atomicAdd(&Sl[gtn * NPRO + m], e);
        }
        float mu = s / (float)KM;
        float var = fmaxf(sq / (float)KM - mu * mu, 0.f);
        float rv = rsqrtf(var + 1e-5f);
        for (int j = 0; j < KM; ++j)
            sim[t * 195 + j] = (sim[t * 195 + j] - mu) * rv * sPg[j] + sPb[j];
    }
    __syncthreads();

    for (int idx = t; idx < 128 * KM; idx += 512) {
        int row = idx / KM, j = idx - row * KM;
        out[OFF_CON + (size_t)bm0 * KM + idx] = sim[row * 195 + j];
    }
    for (int idx = t; idx < 128 * NCLS; idx += 512)
        out[OFF_SEG + (size_t)bm0 * NCLS + idx] = seg_s[idx];
    for (int idx = t; idx < 128 * NPRO; idx += 512)
        g_E[(size_t)bm0 * NPRO + idx] = e_s[idx];
    if (t < NCLS) atomicAdd(&g_Bk[t], bk[t]);
    if (t < KM) atomicAdd(&g_S[t], Sl[t]);
}

// ---------------- 3b: exact pred recompute — 10 parallel partial sums per class ----------------
__global__ void pred_fix(const float* __restrict__ x, const float* __restrict__ fg,
                         const float* __restrict__ fb, const int* __restrict__ gt) {
    int gw = (blockIdx.x * blockDim.x + threadIdx.x) >> 5;
    int lane = threadIdx.x & 31;
    int nwarps = (gridDim.x * blockDim.x) >> 5;
    int nfix = g_nfixA;
    for (int i = gw; i < nfix; i += nwarps) {
        int4 rec = g_fixA[i];
        int n = rec.x;
        float av[23];
        exact_embed(x, fg, fb, n, lane, av);
        int cand[3] = {rec.y, rec.z, rec.w};
        float best = -1e30f; int bi = 0;
        #pragma unroll
        for (int cc = 0; cc < 3; ++cc) {
            int k = cand[cc];
            const float* base = g_Pn + (size_t)k * NPRO * DIMV;
            float sm[NPRO];
            #pragma unroll
            for (int m = 0; m < NPRO; ++m) sm[m] = 0.f;
            #pragma unroll
            for (int j = 0; j < 23; ++j) {
                int d = lane + 32 * j;
                if (d < DIMV) {
                    float a = av[j];
                    #pragma unroll
                    for (int m = 0; m < NPRO; ++m)
                        sm[m] = fmaf(a, base[m * DIMV + d], sm[m]);
                }
            }
            #pragma unroll
            for (int o = 16; o; o >>= 1) {
                #pragma unroll
                for (int m = 0; m < NPRO; ++m)
                    sm[m] += __shfl_xor_sync(0xffffffffu, sm[m], o);
            }
            float mx = sm[0];
            #pragma unroll
            for (int m = 1; m < NPRO; ++m) mx = fmaxf(mx, sm[m]);
            if (mx > best) { best = mx; bi = k; }
        }
        if (lane == 0 && bi == gt[n]) {
            int ii = atomicAdd(&g_ncorr, 1);
            g_corrList[ii] = n;
        }
    }
}

// ---------------- 4: Sinkhorn column-sum accumulation (passes 1,2) ----------------
__global__ void sk_accum(const int* __restrict__ gt) {
    __shared__ float Sl[KM];
    int t = threadIdx.x;
    if (t < KM) Sl[t] = 0.f;
    __syncthreads();
    int n = blockIdx.x * blockDim.x + t;
    if (n < NPIX) {
        int k = gt[n];
        const float* E = g_E + (size_t)n * NPRO;
        float e[NPRO];
        #pragma unroll
        for (int m = 0; m < NPRO; ++m) e[m] = E[m];
        const float* bb = g_b + k * NPRO;
        float d = 0.f;
        #pragma unroll
        for (int m = 0; m < NPRO; ++m) d += e[m] * bb[m];
        float a = 1.f / (g_Bk[k] * d);
        #pragma unroll
        for (int m = 0; m < NPRO; ++m) atomicAdd(&Sl[k * NPRO + m], e[m] * a);
    }
    __syncthreads();
    if (t < KM) atomicAdd(&g_S[t], Sl[t]);
}

__global__ void sk_fin() {
    int t = threadIdx.x;
    if (t < KM) {
        float s = g_S[t];
        g_b[t] = (s > 0.f) ? 1.f / (10.f * s) : 0.f;
        g_S[t] = 0.f;
    }
}

// ---------------- 5: hard assignment + proto_target (top-3 flagging) ----------------
__global__ void sk_final(const int* __restrict__ gt, float* __restrict__ out) {
    int n = blockIdx.x * blockDim.x + threadIdx.x;
    if (n >= NPIX) return;
    int k = gt[n];
    const float* E = g_E + (size_t)n * NPRO;
    const float* bb = g_b + k * NPRO;
    float w1 = -1.f, w2 = -1.f, w3 = -1.f;
    int m1 = 0, m2 = 0, m3 = 0;
    #pragma unroll
    for (int m = 0; m < NPRO; ++m) {
        float wv = E[m] * bb[m];
        if (wv > w1)      { w3 = w2; m3 = m2; w2 = w1; m2 = m1; w1 = wv; m1 = m; }
        else if (wv > w2) { w3 = w2; m3 = m2; w2 = wv; m2 = m; }
        else if (wv > w3) { w3 = wv; m3 = m; }
    }
    out[OFF_PT + n] = (float)(m1 + NPRO * k);
    g_idx[n] = (unsigned char)m1;
    if (w1 - w2 <= TAU_IDX * w1) {
        int ii = atomicAdd(&g_nfixB, 1);
        g_fixB[ii] = make_int4(n, m1, m2, m3);
    }
}

// ---------------- 5b: exact proto-idx recompute — 3 parallel sums ----------------
__global__ void idx_fix(const float* __restrict__ x, const float* __restrict__ fg,
                        const float* __restrict__ fb, const int* __restrict__ gt,
                        float* __restrict__ out) {
    int gw = (blockIdx.x * blockDim.x + threadIdx.x) >> 5;
    int lane = threadIdx.x & 31;
    int nwarps = (gridDim.x * blockDim.x) >> 5;
    int nfix = g_nfixB;
    for (int i = gw; i < nfix; i += nwarps) {
        int4 rec = g_fixB[i];
        int n = rec.x;
        int k = gt[n];
        float av[23];
        exact_embed(x, fg, fb, n, lane, av);
        int cand[3] = {rec.y, rec.z, rec.w};
        float sm[3] = {0.f, 0.f, 0.f};
        const float* p0 = g_Pn + (size_t)(k * NPRO + cand[0]) * DIMV;
        const float* p1 = g_Pn + (size_t)(k * NPRO + cand[1]) * DIMV;
        const float* p2 = g_Pn + (size_t)(k * NPRO + cand[2]) * DIMV;
        #pragma unroll
        for (int j = 0; j < 23; ++j) {
            int d = lane + 32 * j;
            if (d < DIMV) {
                float a = av[j];
                sm[0] = fmaf(a, p0[d], sm[0]);
                sm[1] = fmaf(a, p1[d], sm[1]);
                sm[2] = fmaf(a, p2[d], sm[2]);
            }
        }
        #pragma unroll
        for (int o = 16; o; o >>= 1) {
            #pragma unroll
            for (int cc = 0; cc < 3; ++cc)
                sm[cc] += __shfl_xor_sync(0xffffffffu, sm[cc], o);
        }
        float w1 = -1.f; int bi = 0;
        #pragma unroll
        for (int cc = 0; cc < 3; ++cc) {
            int m = cand[cc];
            float wv = expf(sm[cc] * SKEPS_INV) * g_b[k * NPRO + m];
            if (wv > w1 || (wv == w1 && m < bi)) { w1 = wv; bi = m; }
        }
        if (lane == 0) {
            g_idx[n] = (unsigned char)bi;
            out[OFF_PT + n] = (float)(bi + NPRO * k);
        }
    }
}

// ---------------- 6: accumulate f over correct-pixel list (exact, + n_km) ----------------
__global__ void f_accum(const float* __restrict__ x, const float* __restrict__ fg,
                        const float* __restrict__ fb, const int* __restrict__ gt) {
    int gw = (blockIdx.x * blockDim.x + threadIdx.x) >> 5;
    int lane = threadIdx.x & 31;
    int nwarps = (gridDim.x * blockDim.x) >> 5;
    int nc = g_ncorr;
    for (int i = gw; i < nc; i += nwarps) {
        int n = g_corrList[i];
        int k = gt[n], m = g_idx[n];
        if (lane == 0) atomicAdd(&g_nkm[k * NPRO + m], 1.f);
        float av[23];
        exact_embed(x, fg, fb, n, lane, av);
        float* f = g_f + (size_t)(k * NPRO + m) * DIMV;
        #pragma unroll
        for (int j = 0; j < 23; ++j) {
            int d = lane + 32 * j;
            if (d < DIMV) atomicAdd(&f[d], av[j]);
        }
    }
}

// ---------------- 7: prototype EMA update ----------------
__global__ void update_protos(float* __restrict__ out) {
    int row = blockIdx.x;                 // 0..189
    int k = row / NPRO;
    const float* f = g_f + (size_t)row * DIMV;
    const float* p = g_Pn + (size_t)row * DIMV;

    float sq = 0.f;
    for (int d = threadIdx.x; d < DIMV; d += blockDim.x) { float v = f[d]; sq += v * v; }
    sq = block_sum_256(sq);
    float invf = 1.f / fmaxf(sqrtf(sq), 1e-12f);

    float nk = g_nkm[row];
    float ksum = 0.f;
    #pragma unroll
    for (int m = 0; m < NPRO; ++m) ksum += g_nkm[k * NPRO + m];
    bool valid = (nk != 0.f) && (ksum > 0.f);

    float squ = 0.f;
    for (int d = threadIdx.x; d < DIMV; d += blockDim.x) {
        float pv = p[d];
        float u = valid ? (0.999f * pv + 0.001f * f[d] * invf) : pv;
        squ += u * u;
    }
    squ = block_sum_256(squ);
    float invu = 1.f / fmaxf(sqrtf(squ), 1e-12f);
    for (int d = threadIdx.x; d < DIMV; d += blockDim.x) {
        float pv = p[d];
        float u = valid ? (0.999f * pv + 0.001f * f[d] * invf) : pv;
        out[OFF_PN + (size_t)row * DIMV + d] = u * invu;
    }
}

// ---------------- launch ----------------
extern "C" void kernel_launch(void* const* d_in, const int* in_sizes, int n_in,
                              void* d_out, int out_size) {
    const float* x     = (const float*)d_in[0];
    const float* proto = (const float*)d_in[1];
    const float* fn_g  = (const float*)d_in[2];
    const float* fn_b  = (const float*)d_in[3];
    const float* mn_g  = (const float*)d_in[4];
    const float* mn_b  = (const float*)d_in[5];
    const float* pn_g  = (const float*)d_in[6];
    const float* pn_b  = (const float*)d_in[7];
    const int*   gt    = (const int*)d_in[8];
    float* out = (float*)d_out;

    cudaFuncSetAttribute(gemm_epi, cudaFuncAttributeMaxDynamicSharedMemorySize, DYN_SMEM);

    zero_kernel<<<540, 256>>>();
    norm_protos<<<192, 256>>>(proto);
    prep_pixels<<<NPIX / 8, 256>>>(x, fn_g, fn_b);
    gemm_epi<<<NPIX / 128, 512, DYN_SMEM>>>(mn_g, mn_b, pn_g, pn_b, gt, out);
    pred_fix<<<296, 256>>>(x, fn_g, fn_b, gt);
    sk_fin<<<1, 192>>>();
    sk_accum<<<NPIX / 256, 256>>>(gt);
    sk_fin<<<1, 192>>>();
    sk_accum<<<NPIX / 256, 256>>>(gt);
    sk_fin<<<1, 192>>>();
    sk_final<<<NPIX / 256, 256>>>(gt, out);
    idx_fix<<<296, 256>>>(x, fn_g, fn_b, gt, out);
    f_accum<<<296, 256>>>(x, fn_g, fn_b, gt);
    update_protos<<<KM, 256>>>(out);
}